// round 2
// baseline (speedup 1.0000x reference)
#include <cuda_runtime.h>

// Problem constants
#define Bx 2048
#define Tt 512
#define Dd 6
#define Hh 40
#define Gg 160   // 4*H
#define GP 192   // padded gate stride (f32x2 m=2 overflow region)

#define NWARP 4          // warps per CTA
#define NB 4             // batch elements per warp
#define BPC (NWARP*NB)   // 16 batch per CTA
#define NCTA (Bx/BPC)    // 128 CTAs

// Shared memory layout (in floats)
#define OFF_WI0 0
#define OFF_WH0 (OFF_WI0 + Dd*Gg)        //   960
#define OFF_WI1 (OFF_WH0 + Hh*Gg)        //  7360
#define OFF_WH1 (OFF_WI1 + Hh*Gg)        // 13760
#define OFF_WI2 (OFF_WH1 + Hh*Gg)        // 20160
#define OFF_WH2 (OFF_WI2 + Hh*Gg)        // 26560
#define OFF_PAD (OFF_WH2 + Hh*Gg)        // 32960 (64-float tail pad for m2 overflow)
#define OFF_B0  (OFF_PAD + 64)           // 33024 (GP floats each, padded)
#define OFF_B1  (OFF_B0 + GP)
#define OFF_B2  (OFF_B1 + GP)
#define OFF_WOUT (OFF_B2 + GP)           // 33600
#define OFF_HD0 (OFF_WOUT + Hh)          // 33640  h duplicated pairs: BPC*H*2
#define OFF_HD1 (OFF_HD0 + BPC*Hh*2)
#define OFF_HD2 (OFF_HD1 + BPC*Hh*2)
#define OFF_C0  (OFF_HD2 + BPC*Hh*2)     // 37480  c scalar
#define OFF_C1  (OFF_C0 + BPC*Hh)
#define OFF_C2  (OFF_C1 + BPC*Hh)
#define OFF_GT  (OFF_C2 + BPC*Hh)        // 39400  gates: BPC * GP
#define OFF_XS  (OFF_GT + BPC*GP)        // 42472  x duplicated pairs: BPC*D*2
#define SMEM_FLOATS (OFF_XS + BPC*Dd*2)  // 42664 floats = 170656 B

typedef unsigned long long u64;

__device__ __forceinline__ u64 lds64(unsigned a) {
    u64 v; asm volatile("ld.shared.b64 %0, [%1];" : "=l"(v) : "r"(a)); return v;
}
__device__ __forceinline__ void sts64(unsigned a, u64 v) {
    asm volatile("st.shared.b64 [%0], %1;" :: "r"(a), "l"(v) : "memory");
}
__device__ __forceinline__ u64 ffma2(u64 a, u64 b, u64 c) {
    u64 d; asm("fma.rn.f32x2 %0, %1, %2, %3;" : "=l"(d) : "l"(a), "l"(b), "l"(c)); return d;
}

__device__ __forceinline__ float sigmoidf_(float x) {
    return __fdividef(1.0f, 1.0f + __expf(-x));
}
__device__ __forceinline__ float tanhf_(float x) {
    return __fdividef(2.0f, 1.0f + __expf(-2.0f * x)) - 1.0f;
}

// Gate accumulation, packed f32x2 over gate pairs.
// wl: byte addr of WT[0][2*lane]; row stride 640B; m offsets +256B.
// ha: byte addr of duplicated h (pairs (h,h)), element (b,k) at +(b*K+k)*8.
template<int K>
__device__ __forceinline__ void accum2(u64 acc[3][NB], unsigned wl, unsigned ha)
{
#pragma unroll 4
    for (int k = 0; k < K; k++) {
        u64 w0 = lds64(wl + k * 640);
        u64 w1 = lds64(wl + k * 640 + 256);
        u64 w2 = lds64(wl + k * 640 + 512);
#pragma unroll
        for (int b = 0; b < NB; b++) {
            u64 h = lds64(ha + (b * K + k) * 8);
            acc[0][b] = ffma2(w0, h, acc[0][b]);
            acc[1][b] = ffma2(w1, h, acc[1][b]);
            acc[2][b] = ffma2(w2, h, acc[2][b]);
        }
    }
}

__device__ __forceinline__ void init_bias2(u64 acc[3][NB], unsigned ba)
{
#pragma unroll
    for (int m = 0; m < 3; m++) {
        u64 bv = lds64(ba + m * 256);
#pragma unroll
        for (int b = 0; b < NB; b++) acc[m][b] = bv;
    }
}

__device__ __forceinline__ void store_gates2(const u64 acc[3][NB], unsigned ga)
{
#pragma unroll
    for (int m = 0; m < 3; m++)
#pragma unroll
        for (int b = 0; b < NB; b++)
            sts64(ga + b * (GP * 4) + m * 256, acc[m][b]);
}

// h/c update for the warp's NB*H units (gate order i,f,g,o).
// gsm: scalar float view (stride GP per batch); h written as duplicated pairs.
__device__ __forceinline__ void update_hc(const float* __restrict__ gsm,
                                          unsigned hda,
                                          float* __restrict__ csm, int lane)
{
#pragma unroll
    for (int r = 0; r < 5; r++) {            // NB*H / 32 = 160/32 = 5
        int idx = lane + 32 * r;             // 0..159
        int b = idx / Hh;
        int u = idx - b * Hh;
        float gi = gsm[b * GP + u];
        float gf = gsm[b * GP + 40 + u];
        float gg = gsm[b * GP + 80 + u];
        float go = gsm[b * GP + 120 + u];
        float iv = sigmoidf_(gi);
        float fv = sigmoidf_(gf);
        float gv = tanhf_(gg);
        float ov = sigmoidf_(go);
        float c = fmaf(fv, csm[b * Hh + u], iv * gv);
        csm[b * Hh + u] = c;
        float h = ov * tanhf_(c);
        asm volatile("st.shared.v2.f32 [%0], {%1, %2};"
                     :: "r"(hda + (unsigned)((b * Hh + u) * 8)), "f"(h), "f"(h) : "memory");
    }
}

extern __shared__ float sm[];

__global__ void __launch_bounds__(NWARP * 32, 1)
lstm_fused_kernel(const float* __restrict__ x,
                  const float* __restrict__ Wih0, const float* __restrict__ Whh0,
                  const float* __restrict__ bih0, const float* __restrict__ bhh0,
                  const float* __restrict__ Wih1, const float* __restrict__ Whh1,
                  const float* __restrict__ bih1, const float* __restrict__ bhh1,
                  const float* __restrict__ Wih2, const float* __restrict__ Whh2,
                  const float* __restrict__ bih2, const float* __restrict__ bhh2,
                  const float* __restrict__ Wout, const float* __restrict__ bout,
                  float* __restrict__ out)
{
    const int tid = threadIdx.x;

    // ---- Load weights into shared, transposed: WT[k*G + j] = W[j*K + k] ----
    {
        auto loadT = [&](const float* __restrict__ src, float* __restrict__ dst, int K) {
            for (int idx = tid; idx < Gg * K; idx += NWARP * 32) {
                int j = idx / K;
                int k = idx - j * K;
                dst[k * Gg + j] = src[idx];
            }
        };
        loadT(Wih0, sm + OFF_WI0, Dd);
        loadT(Whh0, sm + OFF_WH0, Hh);
        loadT(Wih1, sm + OFF_WI1, Hh);
        loadT(Whh1, sm + OFF_WH1, Hh);
        loadT(Wih2, sm + OFF_WI2, Hh);
        loadT(Whh2, sm + OFF_WH2, Hh);
        for (int idx = tid; idx < Gg; idx += NWARP * 32) {
            sm[OFF_B0 + idx] = bih0[idx] + bhh0[idx];
            sm[OFF_B1 + idx] = bih1[idx] + bhh1[idx];
            sm[OFF_B2 + idx] = bih2[idx] + bhh2[idx];
        }
        // zero pads (keeps garbage finite; never read into results anyway)
        for (int idx = tid; idx < 64; idx += NWARP * 32) {
            sm[OFF_PAD + idx] = 0.0f;
            sm[OFF_B0 + Gg + (idx & 31)] = 0.0f;
            sm[OFF_B1 + Gg + (idx & 31)] = 0.0f;
            sm[OFF_B2 + Gg + (idx & 31)] = 0.0f;
        }
        if (tid < Hh) sm[OFF_WOUT + tid] = Wout[tid];
        // zero h (duplicated) and c state: HD0..C2 contiguous
        for (int idx = tid; idx < 3 * BPC * Hh * 2 + 3 * BPC * Hh; idx += NWARP * 32)
            sm[OFF_HD0 + idx] = 0.0f;
    }
    __syncthreads();

    const int warp = tid >> 5;
    const int lane = tid & 31;
    const int bw = warp * NB;                         // batch offset inside CTA
    const int bglob = blockIdx.x * BPC + bw;          // global batch base for this warp

    const unsigned sbase = (unsigned)__cvta_generic_to_shared(sm);
    const unsigned laneB = lane * 8;                  // byte offset of this lane's j-pair

    const unsigned wi0 = sbase + OFF_WI0 * 4 + laneB;
    const unsigned wh0 = sbase + OFF_WH0 * 4 + laneB;
    const unsigned wi1 = sbase + OFF_WI1 * 4 + laneB;
    const unsigned wh1 = sbase + OFF_WH1 * 4 + laneB;
    const unsigned wi2 = sbase + OFF_WI2 * 4 + laneB;
    const unsigned wh2 = sbase + OFF_WH2 * 4 + laneB;
    const unsigned b0a = sbase + OFF_B0 * 4 + laneB;
    const unsigned b1a = sbase + OFF_B1 * 4 + laneB;
    const unsigned b2a = sbase + OFF_B2 * 4 + laneB;

    const unsigned hd0 = sbase + (OFF_HD0 + bw * Hh * 2) * 4;
    const unsigned hd1 = sbase + (OFF_HD1 + bw * Hh * 2) * 4;
    const unsigned hd2 = sbase + (OFF_HD2 + bw * Hh * 2) * 4;
    const unsigned xsa = sbase + (OFF_XS + bw * Dd * 2) * 4;
    const unsigned ga  = sbase + (OFF_GT + bw * GP) * 4 + laneB;

    float* gsm = sm + OFF_GT + bw * GP;
    float* c0  = sm + OFF_C0 + bw * Hh;
    float* c1  = sm + OFF_C1 + bw * Hh;
    float* c2  = sm + OFF_C2 + bw * Hh;
    const float* h2s = sm + OFF_HD2 + bw * Hh * 2;    // scalar view of duplicated h2

    const float boutv = bout[0];

    // x streaming: lanes 0..23 each own one (b,k) of the warp's [NB][D] slab.
    const int bb = lane / Dd;                 // 0..5 (only <NB used)
    const int kk = lane - bb * Dd;
    const int bbc = (bb < NB) ? bb : (NB - 1);  // clamp to stay in-bounds
    const float* xptr = x + ((size_t)(bglob + bbc) * Tt) * Dd + kk;
    float xr = xptr[0];                        // x at t=0

    const int ob = lane >> 3;                  // output reduction: b = lane/8
    const int sub = lane & 7;

    for (int t = 0; t < Tt; t++) {
        // stage x_t (duplicated pair) into shared, prefetch x_{t+1}
        if (lane < NB * Dd) {
            asm volatile("st.shared.v2.f32 [%0], {%1, %2};"
                         :: "r"(xsa + (unsigned)((bb * Dd + kk) * 8)), "f"(xr), "f"(xr) : "memory");
        }
        __syncwarp();
        {
            int tn = (t + 1 < Tt) ? (t + 1) : t;
            xr = xptr[tn * Dd];
        }

        u64 acc[3][NB];

        // ---- Layer 0: gates = Wih0@x_t + Whh0@h0 + bias ----
        init_bias2(acc, b0a);
        accum2<Dd>(acc, wi0, xsa);
        accum2<Hh>(acc, wh0, hd0);
        store_gates2(acc, ga);
        __syncwarp();
        update_hc(gsm, hd0, c0, lane);
        __syncwarp();

        // ---- Layer 1 ----
        init_bias2(acc, b1a);
        accum2<Hh>(acc, wi1, hd0);
        accum2<Hh>(acc, wh1, hd1);
        store_gates2(acc, ga);
        __syncwarp();
        update_hc(gsm, hd1, c1, lane);
        __syncwarp();

        // ---- Layer 2 ----
        init_bias2(acc, b2a);
        accum2<Hh>(acc, wi2, hd1);
        accum2<Hh>(acc, wh2, hd2);
        store_gates2(acc, ga);
        __syncwarp();
        update_hc(gsm, hd2, c2, lane);
        __syncwarp();

        // ---- Output projection: out[b,t] = dot(Wout, h2[b]) + bout ----
        float s = 0.0f;
#pragma unroll
        for (int q = 0; q < 5; q++) {
            int u = sub * 5 + q;
            s = fmaf(sm[OFF_WOUT + u], h2s[(ob * Hh + u) * 2], s);
        }
        s += __shfl_down_sync(0xffffffffu, s, 4, 8);
        s += __shfl_down_sync(0xffffffffu, s, 2, 8);
        s += __shfl_down_sync(0xffffffffu, s, 1, 8);
        if (sub == 0) out[(size_t)(bglob + ob) * Tt + t] = s + boutv;
        __syncwarp();
    }
}

extern "C" void kernel_launch(void* const* d_in, const int* in_sizes, int n_in,
                              void* d_out, int out_size)
{
    const float* x    = (const float*)d_in[0];
    const float* Wih0 = (const float*)d_in[1];
    const float* Whh0 = (const float*)d_in[2];
    const float* bih0 = (const float*)d_in[3];
    const float* bhh0 = (const float*)d_in[4];
    const float* Wih1 = (const float*)d_in[5];
    const float* Whh1 = (const float*)d_in[6];
    const float* bih1 = (const float*)d_in[7];
    const float* bhh1 = (const float*)d_in[8];
    const float* Wih2 = (const float*)d_in[9];
    const float* Whh2 = (const float*)d_in[10];
    const float* bih2 = (const float*)d_in[11];
    const float* bhh2 = (const float*)d_in[12];
    const float* Wout = (const float*)d_in[13];
    const float* bout = (const float*)d_in[14];
    float* out = (float*)d_out;

    (void)in_sizes; (void)n_in; (void)out_size;

    cudaFuncSetAttribute(lstm_fused_kernel,
                         cudaFuncAttributeMaxDynamicSharedMemorySize,
                         SMEM_FLOATS * (int)sizeof(float));

    lstm_fused_kernel<<<NCTA, NWARP * 32, SMEM_FLOATS * sizeof(float)>>>(
        x, Wih0, Whh0, bih0, bhh0, Wih1, Whh1, bih1, bhh1,
        Wih2, Whh2, bih2, bhh2, Wout, bout, out);
}